// round 9
// baseline (speedup 1.0000x reference)
#include <cuda_runtime.h>
#include <cuda_bf16.h>
#include <math.h>

// ---------------------------------------------------------------------------
// Problem constants
// ---------------------------------------------------------------------------
#define BB    4          // batch
#define BPTT  16
#define PRED  4
#define SS    20         // S = BPTT + PRED
#define VV    512        // 8*8*8 voxels
#define EE    256
#define NHH   8
#define HEADD 32
#define HIDD  512
#define NEE   512
#define FF    80         // B * S frames

#define FVE   ((size_t)FF * VV * EE)    // 10,485,760
#define FVH   ((size_t)FF * VV * HIDD)  // 20,971,520
#define SCORE_SIZE (BB * NEE * PRED * VV)  // 4,194,304
#define NROWS (BB * PRED * VV)             // 8192

// ---------------------------------------------------------------------------
// Scratch (allocation-free: __device__ globals)
// ---------------------------------------------------------------------------
__device__ float g_x[FVE];
__device__ float g_h[FVE];
__device__ float g_q[FVE];
__device__ float g_k[FVE];
__device__ float g_v[FVE];
__device__ float g_ao[FVE];
__device__ float g_hid[FVH];
__device__ float g_logits[FVH];
__device__ float g_rowloss[NROWS];

// ---------------------------------------------------------------------------
// Packed fp32x2 helpers (sm_100+). Numerically identical to 2x scalar FFMA.
// ---------------------------------------------------------------------------
__device__ __forceinline__ unsigned long long dup_f32x2(float x) {
    unsigned long long r;
    asm("mov.b64 %0, {%1, %1};" : "=l"(r) : "f"(x));
    return r;
}
__device__ __forceinline__ void fma_f32x2(unsigned long long& acc,
                                          unsigned long long a,
                                          unsigned long long b) {
    asm("fma.rn.f32x2 %0, %1, %2, %0;" : "+l"(acc) : "l"(a), "l"(b));
}
__device__ __forceinline__ void unpack_f32x2(unsigned long long p, float& lo, float& hi) {
    asm("mov.b64 {%0, %1}, %2;" : "=f"(lo), "=f"(hi) : "l"(p));
}
union F4U2 { float4 f; unsigned long long u[2]; };

// ---------------------------------------------------------------------------
// Embedding: x[b,s,v,e] = emb[tok][e] + pos[s][e]
// ---------------------------------------------------------------------------
__global__ void embed_kernel(const int* __restrict__ code,
                             const float* __restrict__ emb,
                             const float* __restrict__ pos,
                             float* __restrict__ x)
{
    size_t idx = (size_t)blockIdx.x * blockDim.x + threadIdx.x;
    if (idx >= FVE) return;
    int e = (int)(idx & 255);
    int v = (int)((idx >> 8) & 511);
    int f = (int)(idx >> 17);            // /(256*512)
    int b = f / SS, s = f % SS;
    int tok = (s < BPTT) ? code[((b * BPTT + s) << 9) + v] : NEE;
    x[idx] = emb[tok * EE + e] + pos[s * EE + e];
}

// ---------------------------------------------------------------------------
// LayerNorm over last dim (E=256), warp per row
// ---------------------------------------------------------------------------
__global__ void ln_kernel(const float* __restrict__ in, float* __restrict__ out,
                          const float* __restrict__ sc, const float* __restrict__ bi,
                          int rows)
{
    int wid  = (int)((blockIdx.x * blockDim.x + threadIdx.x) >> 5);
    int lane = threadIdx.x & 31;
    if (wid >= rows) return;
    const float* p = in + (size_t)wid * EE;
    float v8[8];
    float s = 0.f, sq = 0.f;
#pragma unroll
    for (int i = 0; i < 8; ++i) {
        float xv = p[lane + i * 32];
        v8[i] = xv;
        s += xv;
        sq = fmaf(xv, xv, sq);
    }
#pragma unroll
    for (int off = 16; off > 0; off >>= 1) {
        s  += __shfl_xor_sync(0xffffffffu, s, off);
        sq += __shfl_xor_sync(0xffffffffu, sq, off);
    }
    float m   = s * (1.f / 256.f);
    float var = sq * (1.f / 256.f) - m * m;
    if (var < 0.f) var = 0.f;
    float inv = rsqrtf(var + 1e-5f);
    float* q = out + (size_t)wid * EE;
#pragma unroll
    for (int i = 0; i < 8; ++i) {
        int e = lane + i * 32;
        q[e] = (v8[i] - m) * inv * sc[e] + bi[e];
    }
}

// ---------------------------------------------------------------------------
// 3D conv, 3x3x3, SAME padding, implicit GEMM.
//   x: [F][512][Cin]   w: [27][Cin][Cout]   y: [F][512][Cout]
// Block: one frame f, one 64-wide cout tile, one 2-slice z quarter.
// cin chunk = 4; smem 40.4KB/CTA -> 4 CTAs/SM.
// Activations stored in smem PRE-DUPLICATED as (x,x) 8-byte pairs;
// mainloop loads the 10-value halo row as 5 x LDS.128 (two dup-pairs each):
// zero dup movs, zero bank conflicts (8 rows x 80B stride covers all banks).
// Weights ws[27][4ch][64co]. Lane map: warp = 4 cout-octets x 8 rows.
// FMAs are packed fma.rn.f32x2 over cout pairs.
// ---------------------------------------------------------------------------
#define KCH 4
#define CONV_SMEM_BYTES (KCH * 400 * 8 + 27 * KCH * 64 * 4)  // 12800+27648=40448

__global__ void __launch_bounds__(128, 4)
conv3d_kernel(const float* __restrict__ x, const float* __restrict__ w,
              const float* __restrict__ bias, const float* __restrict__ residual,
              float* __restrict__ y, int Cin, int Cout, int do_gelu)
{
    extern __shared__ float smem[];
    unsigned long long* xs64 = (unsigned long long*)smem;   // [4][400] dup pairs
    float* ws = smem + KCH * 800;                            // [27][4][64]

    const int t     = threadIdx.x;
    const int f     = blockIdx.x;
    const int co0   = blockIdx.y * 64;
    const int zbase = blockIdx.z * 2;

    // lane map: warp covers 4 cout-octets x 8 rows
    const int cg  = (t & 3) | (((t >> 5) & 1) << 2);          // 0..7 cout octet
    const int row = ((t >> 2) & 7) | (((t >> 6) & 1) << 3);   // 0..15
    const int zl = row >> 3;     // 0..1
    const int gy = row & 7;      // 0..7

    for (int i = t; i < KCH * 400; i += 128) xs64[i] = 0ull;

    unsigned long long acc[8][4];
#pragma unroll
    for (int j = 0; j < 8; ++j)
#pragma unroll
        for (int c = 0; c < 4; ++c) acc[j][c] = 0ull;

    const float* xf = x + (size_t)f * VV * Cin;
    const int nch = Cin / KCH;

    for (int kc = 0; kc < nch; ++kc) {
        __syncthreads();
        // ---- fill activation chunk (4 z-slices incl halo, 8x8 each, 4 ch)
        //      stored as duplicated (x,x) 8-byte pairs
#pragma unroll
        for (int rep = 0; rep < 2; ++rep) {
            int j  = t + rep * 128;      // 0..255
            int lz = j >> 6;             // 0..3  (pz directly)
            int vy = (j >> 3) & 7;
            int vx = j & 7;
            int gz = zbase + lz - 1;
            float val[KCH];
            if ((unsigned)gz < 8u) {
                float4 r0 = *(const float4*)(xf + (size_t)(gz * 64 + vy * 8 + vx) * Cin + kc * KCH);
                val[0] = r0.x; val[1] = r0.y; val[2] = r0.z; val[3] = r0.w;
            } else {
#pragma unroll
                for (int kk = 0; kk < KCH; ++kk) val[kk] = 0.f;
            }
            int p = lz * 100 + (vy + 1) * 10 + (vx + 1);
#pragma unroll
            for (int kk = 0; kk < KCH; ++kk) xs64[kk * 400 + p] = dup_f32x2(val[kk]);
        }
        // ---- fill weight chunk: 27*4*64 floats = 1728 float4
        {
            float4* wd = (float4*)ws;
            for (int i = t; i < 1728; i += 128) {
                int o  = i >> 6;         // /64 (64 float4 per tap)
                int r  = i & 63;
                int kk = r >> 4;         // /16  (16 float4 per cin)
                int c4 = r & 15;
                wd[i] = *(const float4*)&w[((size_t)o * Cin + (kc * KCH + kk)) * Cout + co0 + c4 * 4];
            }
        }
        __syncthreads();

        const float4* ws4 = (const float4*)ws;
#pragma unroll 1
        for (int kk = 0; kk < KCH; ++kk) {
            const unsigned long long* xkk = xs64 + kk * 400;
            const float4* wk4 = ws4 + kk * 16 + cg * 2;
#pragma unroll 1
            for (int dz = 0; dz < 3; ++dz) {
#pragma unroll 1
                for (int dy = 0; dy < 3; ++dy) {
                    // 10 dup-pairs via 5 independent LDS.128 (16B-aligned rows)
                    const ulonglong2* rp = (const ulonglong2*)(xkk + (zl + dz) * 100 + (gy + dy) * 10);
                    ulonglong2 q0 = rp[0], q1 = rp[1], q2 = rp[2], q3 = rp[3], q4 = rp[4];
                    unsigned long long rd[10];
                    rd[0] = q0.x; rd[1] = q0.y;
                    rd[2] = q1.x; rd[3] = q1.y;
                    rd[4] = q2.x; rd[5] = q2.y;
                    rd[6] = q3.x; rd[7] = q3.y;
                    rd[8] = q4.x; rd[9] = q4.y;
                    const float4* wo4 = wk4 + (size_t)(dz * 9 + dy * 3) * KCH * 16;
#pragma unroll
                    for (int dx = 0; dx < 3; ++dx) {
                        F4U2 b0, b1;
                        b0.f = wo4[(size_t)dx * KCH * 16];
                        b1.f = wo4[(size_t)dx * KCH * 16 + 1];
                        unsigned long long bp0 = b0.u[0], bp1 = b0.u[1];
                        unsigned long long bp2 = b1.u[0], bp3 = b1.u[1];
#pragma unroll
                        for (int j = 0; j < 8; ++j) {
                            unsigned long long a2 = rd[j + dx];
                            fma_f32x2(acc[j][0], a2, bp0);
                            fma_f32x2(acc[j][1], a2, bp1);
                            fma_f32x2(acc[j][2], a2, bp2);
                            fma_f32x2(acc[j][3], a2, bp3);
                        }
                    }
                }
            }
        }
    }

    // ---- epilogue: bias (+residual) (+gelu)
    int co = co0 + cg * 8;
    float bv[8];
#pragma unroll
    for (int c = 0; c < 8; ++c) bv[c] = bias[co + c];
#pragma unroll
    for (int j = 0; j < 8; ++j) {
        int vox = (zbase + zl) * 64 + gy * 8 + j;
        size_t oi = ((size_t)f * VV + vox) * Cout + co;
        float r[8];
#pragma unroll
        for (int c = 0; c < 4; ++c) {
            float lo, hi;
            unpack_f32x2(acc[j][c], lo, hi);
            r[2 * c]     = lo + bv[2 * c];
            r[2 * c + 1] = hi + bv[2 * c + 1];
        }
        if (residual) {
            const float4* rp = (const float4*)(residual + oi);
            float4 r0 = rp[0], r1 = rp[1];
            r[0] += r0.x; r[1] += r0.y; r[2] += r0.z; r[3] += r0.w;
            r[4] += r1.x; r[5] += r1.y; r[6] += r1.z; r[7] += r1.w;
        }
        if (do_gelu) {
#pragma unroll
            for (int c = 0; c < 8; ++c)
                r[c] = 0.5f * r[c] * (1.f + erff(r[c] * 0.7071067811865475f));
        }
        float4* op = (float4*)(y + oi);
        op[0] = make_float4(r[0], r[1], r[2], r[3]);
        op[1] = make_float4(r[4], r[5], r[6], r[7]);
    }
}

// ---------------------------------------------------------------------------
// Attention over time (20 steps) per (b, voxel, head). One warp per unit.
// ---------------------------------------------------------------------------
__global__ void __launch_bounds__(128)
attn_kernel(const float* __restrict__ q, const float* __restrict__ k,
            const float* __restrict__ v, float* __restrict__ o)
{
    __shared__ float sm[4][2380];   // per warp: q 20x33, k 20x33, v 20x33, at 20x20
    int wlocal = threadIdx.x >> 5;
    int lane   = threadIdx.x & 31;
    int wid    = blockIdx.x * 4 + wlocal;     // 0..16383 (B*V*NH)
    int h  = wid & 7;
    int vx = (wid >> 3) & 511;
    int b  = wid >> 12;

    float* qs = sm[wlocal];
    float* ks = qs + 660;
    float* vs = ks + 660;
    float* at = vs + 660;

    size_t base = (size_t)vx * EE + h * HEADD + lane;
#pragma unroll
    for (int s = 0; s < SS; ++s) {
        size_t gi = (size_t)(b * SS + s) * (VV * EE) + base;
        qs[s * 33 + lane] = q[gi];
        ks[s * 33 + lane] = k[gi];
        vs[s * 33 + lane] = v[gi];
    }
    __syncwarp();

    const float scale = 0.17677669529663687f;  // 1/sqrt(32)
    int tt = lane;
#pragma unroll 1
    for (int s = 0; s < SS; ++s) {
        float sc = -1e30f;
        if (tt < SS) {
            float a = 0.f;
#pragma unroll
            for (int d = 0; d < HEADD; ++d)
                a = fmaf(qs[s * 33 + d], ks[tt * 33 + d], a);
            sc = a * scale;
        }
        float m = sc;
#pragma unroll
        for (int off = 16; off > 0; off >>= 1)
            m = fmaxf(m, __shfl_xor_sync(0xffffffffu, m, off));
        float e = (tt < SS) ? expf(sc - m) : 0.f;
        float su = e;
#pragma unroll
        for (int off = 16; off > 0; off >>= 1)
            su += __shfl_xor_sync(0xffffffffu, su, off);
        if (tt < SS) at[s * SS + tt] = e / su;
    }
    __syncwarp();

#pragma unroll 1
    for (int s = 0; s < SS; ++s) {
        float a = 0.f;
#pragma unroll
        for (int t2 = 0; t2 < SS; ++t2)
            a = fmaf(at[s * SS + t2], vs[t2 * 33 + lane], a);
        o[(size_t)(b * SS + s) * (VV * EE) + base] = a;
    }
}

// ---------------------------------------------------------------------------
// Final linear: [40960 x 256] @ [256 x 512] + bias -> logits
// ---------------------------------------------------------------------------
__global__ void __launch_bounds__(256)
linear_kernel(const float* __restrict__ A, const float* __restrict__ Bw,
              const float* __restrict__ bias, float* __restrict__ C)
{
    __shared__ float As[32 * 65];
    __shared__ float Bs[32 * 64];
    int t  = threadIdx.x;
    int tx = t & 15, ty = t >> 4;
    int m0 = blockIdx.x * 64, n0 = blockIdx.y * 64;
    float acc[4][4];
#pragma unroll
    for (int i = 0; i < 4; ++i)
#pragma unroll
        for (int j = 0; j < 4; ++j) acc[i][j] = 0.f;

    for (int kt = 0; kt < 8; ++kt) {
        for (int i = t; i < 2048; i += 256) {
            int r = i >> 5, kk = i & 31;
            As[kk * 65 + r] = A[(size_t)(m0 + r) * EE + kt * 32 + kk];
        }
        for (int i = t; i < 2048; i += 256) {
            int kk = i >> 6, c = i & 63;
            Bs[kk * 64 + c] = Bw[(size_t)(kt * 32 + kk) * NEE + n0 + c];
        }
        __syncthreads();
#pragma unroll
        for (int kk = 0; kk < 32; ++kk) {
            float a[4];
#pragma unroll
            for (int i = 0; i < 4; ++i) a[i] = As[kk * 65 + ty * 4 + i];
            float4 bvv = *(const float4*)&Bs[kk * 64 + tx * 4];
            float bvals[4] = {bvv.x, bvv.y, bvv.z, bvv.w};
#pragma unroll
            for (int i = 0; i < 4; ++i)
#pragma unroll
                for (int j = 0; j < 4; ++j)
                    acc[i][j] = fmaf(a[i], bvals[j], acc[i][j]);
        }
        __syncthreads();
    }
#pragma unroll
    for (int i = 0; i < 4; ++i)
#pragma unroll
        for (int j = 0; j < 4; ++j)
            C[(size_t)(m0 + ty * 4 + i) * NEE + n0 + tx * 4 + j] =
                acc[i][j] + bias[n0 + tx * 4 + j];
}

// ---------------------------------------------------------------------------
// Score transpose: score[b][c][p][v] = logits[b*20+16+p][v][c]
// ---------------------------------------------------------------------------
__global__ void score_kernel(const float* __restrict__ logits, float* __restrict__ out,
                             int out_size)
{
    __shared__ float tile[32][33];
    int bp = blockIdx.z;
    int b = bp >> 2, p = bp & 3;
    int v0 = blockIdx.x * 32, c0 = blockIdx.y * 32;
    int f = b * SS + BPTT + p;
    int t = threadIdx.x;
    int ci = t & 31, vi = t >> 5;     // vi 0..7
#pragma unroll
    for (int r = 0; r < 32; r += 8)
        tile[vi + r][ci] = logits[((size_t)f * VV + v0 + vi + r) * NEE + c0 + ci];
    __syncthreads();
    int vv2 = t & 31, cc = t >> 5;
#pragma unroll
    for (int r = 0; r < 32; r += 8) {
        size_t oidx = (((size_t)(b * NEE + c0 + cc + r)) * PRED + p) * VV + v0 + vv2;
        if (oidx < (size_t)out_size) out[oidx] = tile[vv2][cc + r];
    }
}

// ---------------------------------------------------------------------------
// Per-row log-softmax target loss + argmax. Warp per (b,p,v) row.
// ---------------------------------------------------------------------------
__global__ void loss_argmax_kernel(const float* __restrict__ logits,
                                   const int* __restrict__ ncode,
                                   float* __restrict__ rowloss,
                                   float* __restrict__ out, int write_code)
{
    int wid  = (int)((blockIdx.x * blockDim.x + threadIdx.x) >> 5);
    int lane = threadIdx.x & 31;
    if (wid >= NROWS) return;
    int v = wid & 511, p = (wid >> 9) & 3, b = wid >> 11;
    const float* lp = logits + ((size_t)(b * SS + BPTT + p) * VV + v) * NEE;

    float vals[16];
    float mx = -1e30f;
    int mi = 0;
#pragma unroll
    for (int i = 0; i < 16; ++i) {
        int c = lane + i * 32;
        float xv = lp[c];
        vals[i] = xv;
        if (xv > mx) { mx = xv; mi = c; }
    }
#pragma unroll
    for (int off = 16; off > 0; off >>= 1) {
        float om = __shfl_xor_sync(0xffffffffu, mx, off);
        int   oi = __shfl_xor_sync(0xffffffffu, mi, off);
        if (om > mx || (om == mx && oi < mi)) { mx = om; mi = oi; }
    }
    float se = 0.f;
#pragma unroll
    for (int i = 0; i < 16; ++i) se += expf(vals[i] - mx);
#pragma unroll
    for (int off = 16; off > 0; off >>= 1)
        se += __shfl_xor_sync(0xffffffffu, se, off);

    int tgt = ncode[wid];
    if (lane == (tgt & 31))
        rowloss[wid] = -(vals[tgt >> 5] - mx - logf(se));
    if (write_code && lane == 0)
        out[(size_t)SCORE_SIZE + 1 + wid] = (float)mi;
}

__global__ void loss_reduce_kernel(const float* __restrict__ rowloss,
                                   float* __restrict__ out, int loss_off)
{
    __shared__ float smr[256];
    int t = threadIdx.x;
    float a = 0.f;
    for (int i = t; i < NROWS; i += 256) a += rowloss[i];
    smr[t] = a;
    __syncthreads();
    for (int s = 128; s > 0; s >>= 1) {
        if (t < s) smr[t] += smr[t + s];
        __syncthreads();
    }
    if (t == 0) out[loss_off] = smr[0] * (1.f / (float)NROWS);
}

// ---------------------------------------------------------------------------
// Orchestration
// ---------------------------------------------------------------------------
extern "C" void kernel_launch(void* const* d_in, const int* in_sizes, int n_in,
                              void* d_out, int out_size)
{
    (void)in_sizes; (void)n_in;
    const int*   code   = (const int*)  d_in[0];
    const int*   ncode  = (const int*)  d_in[1];
    const float* emb    = (const float*)d_in[2];
    const float* pos    = (const float*)d_in[3];
    const float* ln1s   = (const float*)d_in[4];
    const float* ln1b   = (const float*)d_in[5];
    const float* ln2s   = (const float*)d_in[6];
    const float* ln2b   = (const float*)d_in[7];
    const float* wq     = (const float*)d_in[8];
    const float* bq     = (const float*)d_in[9];
    const float* wk     = (const float*)d_in[10];
    const float* bk     = (const float*)d_in[11];
    const float* wv     = (const float*)d_in[12];
    const float* bv     = (const float*)d_in[13];
    const float* wo     = (const float*)d_in[14];
    const float* bo     = (const float*)d_in[15];
    const float* w1     = (const float*)d_in[16];
    const float* b1     = (const float*)d_in[17];
    const float* w2     = (const float*)d_in[18];
    const float* b2     = (const float*)d_in[19];
    const float* lnfs   = (const float*)d_in[20];
    const float* lnfb   = (const float*)d_in[21];
    const float* decw   = (const float*)d_in[22];
    const float* decb   = (const float*)d_in[23];
    const float* declns = (const float*)d_in[24];
    const float* declnb = (const float*)d_in[25];
    const float* linw   = (const float*)d_in[26];
    const float* linb   = (const float*)d_in[27];
    float* out = (float*)d_out;

    float *px, *ph, *pq, *pk, *pv, *pa, *phid, *plog, *prl;
    cudaGetSymbolAddress((void**)&px,   g_x);
    cudaGetSymbolAddress((void**)&ph,   g_h);
    cudaGetSymbolAddress((void**)&pq,   g_q);
    cudaGetSymbolAddress((void**)&pk,   g_k);
    cudaGetSymbolAddress((void**)&pv,   g_v);
    cudaGetSymbolAddress((void**)&pa,   g_ao);
    cudaGetSymbolAddress((void**)&phid, g_hid);
    cudaGetSymbolAddress((void**)&plog, g_logits);
    cudaGetSymbolAddress((void**)&prl,  g_rowloss);

    cudaFuncSetAttribute(conv3d_kernel,
                         cudaFuncAttributeMaxDynamicSharedMemorySize,
                         CONV_SMEM_BYTES);

    const int ROWS = FF * VV;                  // 40960
    const int LN_BLOCKS = (ROWS * 32) / 256;   // 5120
    const size_t WEE = 27 * 256 * 256;         // per-layer E->E weight stride
    const size_t WEH = 27 * 256 * 512;         // per-layer E->HID (== HID->E)

    embed_kernel<<<(int)((FVE + 255) / 256), 256>>>(code, emb, pos, px);

    dim3 cgE(FF, 4, 4);   // Cout=256
    dim3 cgH(FF, 8, 4);   // Cout=512
    for (int i = 0; i < 4; ++i) {
        ln_kernel<<<LN_BLOCKS, 256>>>(px, ph, ln1s + i * EE, ln1b + i * EE, ROWS);
        conv3d_kernel<<<cgE, 128, CONV_SMEM_BYTES>>>(ph, wq + i * WEE, bq + i * EE, nullptr, pq, 256, 256, 0);
        conv3d_kernel<<<cgE, 128, CONV_SMEM_BYTES>>>(ph, wk + i * WEE, bk + i * EE, nullptr, pk, 256, 256, 0);
        conv3d_kernel<<<cgE, 128, CONV_SMEM_BYTES>>>(ph, wv + i * WEE, bv + i * EE, nullptr, pv, 256, 256, 0);
        attn_kernel<<<4096, 128>>>(pq, pk, pv, pa);
        conv3d_kernel<<<cgE, 128, CONV_SMEM_BYTES>>>(pa, wo + i * WEE, bo + i * EE, px, px, 256, 256, 0);
        ln_kernel<<<LN_BLOCKS, 256>>>(px, ph, ln2s + i * EE, ln2b + i * EE, ROWS);
        conv3d_kernel<<<cgH, 128, CONV_SMEM_BYTES>>>(ph, w1 + i * WEH, b1 + i * HIDD, nullptr, phid, 256, 512, 1);
        conv3d_kernel<<<cgE, 128, CONV_SMEM_BYTES>>>(phid, w2 + i * WEH, b2 + i * EE, px, px, 512, 256, 0);
    }

    ln_kernel<<<LN_BLOCKS, 256>>>(px, ph, lnfs, lnfb, ROWS);
    conv3d_kernel<<<cgE, 128, CONV_SMEM_BYTES>>>(ph, decw, decb, nullptr, pq, 256, 256, 1);
    ln_kernel<<<LN_BLOCKS, 256>>>(pq, pk, declns, declnb, ROWS);
    linear_kernel<<<dim3(ROWS / 64, NEE / 64), 256>>>(pk, linw, linb, plog);

    if (out_size >= SCORE_SIZE) {
        dim3 sg(16, 16, 16);
        score_kernel<<<sg, 256>>>(plog, out, out_size);
    }
    int write_code = (out_size >= SCORE_SIZE + 1 + NROWS) ? 1 : 0;
    loss_argmax_kernel<<<(NROWS * 32) / 256, 256>>>(plog, ncode, prl, out, write_code);

    int loss_off = -1;
    if (out_size == 1) loss_off = 0;
    else if (out_size > SCORE_SIZE) loss_off = SCORE_SIZE;
    if (loss_off >= 0)
        loss_reduce_kernel<<<1, 256>>>(prl, out, loss_off);
}

// round 10
// speedup vs baseline: 1.2209x; 1.2209x over previous
#include <cuda_runtime.h>
#include <cuda_bf16.h>
#include <math.h>

// ---------------------------------------------------------------------------
// Problem constants
// ---------------------------------------------------------------------------
#define BB    4          // batch
#define BPTT  16
#define PRED  4
#define SS    20         // S = BPTT + PRED
#define VV    512        // 8*8*8 voxels
#define EE    256
#define NHH   8
#define HEADD 32
#define HIDD  512
#define NEE   512
#define FF    80         // B * S frames

#define FVE   ((size_t)FF * VV * EE)    // 10,485,760
#define FVH   ((size_t)FF * VV * HIDD)  // 20,971,520
#define SCORE_SIZE (BB * NEE * PRED * VV)  // 4,194,304
#define NROWS (BB * PRED * VV)             // 8192

// ---------------------------------------------------------------------------
// Scratch (allocation-free: __device__ globals)
// ---------------------------------------------------------------------------
__device__ float g_x[FVE];
__device__ float g_h[FVE];
__device__ float g_q[FVE];
__device__ float g_k[FVE];
__device__ float g_v[FVE];
__device__ float g_ao[FVE];
__device__ float g_hid[FVH];
__device__ float g_logits[FVH];
__device__ float g_rowloss[NROWS];

// ---------------------------------------------------------------------------
// Packed fp32x2 helpers (sm_100+). Numerically identical to 2x scalar FFMA.
// ---------------------------------------------------------------------------
__device__ __forceinline__ unsigned long long dup_f32x2(float x) {
    unsigned long long r;
    asm("mov.b64 %0, {%1, %1};" : "=l"(r) : "f"(x));
    return r;
}
__device__ __forceinline__ void fma_f32x2(unsigned long long& acc,
                                          unsigned long long a,
                                          unsigned long long b) {
    asm("fma.rn.f32x2 %0, %1, %2, %0;" : "+l"(acc) : "l"(a), "l"(b));
}
__device__ __forceinline__ void unpack_f32x2(unsigned long long p, float& lo, float& hi) {
    asm("mov.b64 {%0, %1}, %2;" : "=f"(lo), "=f"(hi) : "l"(p));
}
union F4U2 { float4 f; unsigned long long u[2]; };

__device__ __forceinline__ void cp_async16(unsigned int dst, const float* src) {
    asm volatile("cp.async.cg.shared.global [%0], [%1], 16;"
                 :: "r"(dst), "l"(src) : "memory");
}

// ---------------------------------------------------------------------------
// Embedding: x[b,s,v,e] = emb[tok][e] + pos[s][e]
// ---------------------------------------------------------------------------
__global__ void embed_kernel(const int* __restrict__ code,
                             const float* __restrict__ emb,
                             const float* __restrict__ pos,
                             float* __restrict__ x)
{
    size_t idx = (size_t)blockIdx.x * blockDim.x + threadIdx.x;
    if (idx >= FVE) return;
    int e = (int)(idx & 255);
    int v = (int)((idx >> 8) & 511);
    int f = (int)(idx >> 17);            // /(256*512)
    int b = f / SS, s = f % SS;
    int tok = (s < BPTT) ? code[((b * BPTT + s) << 9) + v] : NEE;
    x[idx] = emb[tok * EE + e] + pos[s * EE + e];
}

// ---------------------------------------------------------------------------
// LayerNorm over last dim (E=256), warp per row
// ---------------------------------------------------------------------------
__global__ void ln_kernel(const float* __restrict__ in, float* __restrict__ out,
                          const float* __restrict__ sc, const float* __restrict__ bi,
                          int rows)
{
    int wid  = (int)((blockIdx.x * blockDim.x + threadIdx.x) >> 5);
    int lane = threadIdx.x & 31;
    if (wid >= rows) return;
    const float* p = in + (size_t)wid * EE;
    float v8[8];
    float s = 0.f, sq = 0.f;
#pragma unroll
    for (int i = 0; i < 8; ++i) {
        float xv = p[lane + i * 32];
        v8[i] = xv;
        s += xv;
        sq = fmaf(xv, xv, sq);
    }
#pragma unroll
    for (int off = 16; off > 0; off >>= 1) {
        s  += __shfl_xor_sync(0xffffffffu, s, off);
        sq += __shfl_xor_sync(0xffffffffu, sq, off);
    }
    float m   = s * (1.f / 256.f);
    float var = sq * (1.f / 256.f) - m * m;
    if (var < 0.f) var = 0.f;
    float inv = rsqrtf(var + 1e-5f);
    float* q = out + (size_t)wid * EE;
#pragma unroll
    for (int i = 0; i < 8; ++i) {
        int e = lane + i * 32;
        q[e] = (v8[i] - m) * inv * sc[e] + bi[e];
    }
}

// ---------------------------------------------------------------------------
// 3D conv, 3x3x3, SAME padding, implicit GEMM. 2-stage pipelined.
//   x: [F][512][Cin]   w: [27][Cin][Cout]   y: [F][512][Cout]
// Block: one frame f, one 64-wide cout tile, one 2-slice z quarter.
// cin chunk = 4. Double-buffered smem (68KB -> 3 CTAs/SM):
//   weights prefetched via cp.async (contiguous 16B), activations
//   prefetched to registers and STS'd at iteration top. Fill of chunk k+1
//   overlaps compute of chunk k; only barriers remain exposed.
// Compute loop = proven R7 codegen: 5 LDS.64 + dup movs + fma.rn.f32x2.
// ---------------------------------------------------------------------------
#define KCH 4
#define XS_F (KCH * 400)            // 1600 floats
#define WS_F (27 * KCH * 64)        // 6912 floats
#define STG_F (XS_F + WS_F)         // 8512 floats
#define CONV_SMEM_BYTES (2 * STG_F * 4)   // 68096

__global__ void __launch_bounds__(128, 3)
conv3d_kernel(const float* __restrict__ x, const float* __restrict__ w,
              const float* __restrict__ bias, const float* __restrict__ residual,
              float* __restrict__ y, int Cin, int Cout, int do_gelu)
{
    extern __shared__ float smem[];
    const int t     = threadIdx.x;
    const int f     = blockIdx.x;
    const int co0   = blockIdx.y * 64;
    const int zbase = blockIdx.z * 2;

    // lane map: warp covers 4 cout-octets x 8 rows
    const int cg  = (t & 3) | (((t >> 5) & 1) << 2);          // 0..7 cout octet
    const int row = ((t >> 2) & 7) | (((t >> 6) & 1) << 3);   // 0..15
    const int zl = row >> 3;     // 0..1
    const int gy = row & 7;      // 0..7

    float* xsb0 = smem;
    float* xsb1 = smem + STG_F;
    float* wsb0 = smem + XS_F;
    float* wsb1 = smem + STG_F + XS_F;
    unsigned int wsu0 = (unsigned int)__cvta_generic_to_shared(wsb0);
    unsigned int wsu1 = (unsigned int)__cvta_generic_to_shared(wsb1);

    // zero activation halos in both stages (interior rewritten every chunk)
    for (int i = t; i < XS_F; i += 128) { xsb0[i] = 0.f; xsb1[i] = 0.f; }

    // activation source positions for this thread's two elements
    const float* xf = x + (size_t)f * VV * Cin;
    const float* asrc[2]; int ap[2]; bool aok[2];
#pragma unroll
    for (int r = 0; r < 2; ++r) {
        int j  = t + r * 128;
        int lz = j >> 6, vy = (j >> 3) & 7, vx = j & 7;
        int gz = zbase + lz - 1;
        aok[r]  = ((unsigned)gz < 8u);
        asrc[r] = xf + (size_t)(gz * 64 + vy * 8 + vx) * Cin;
        ap[r]   = lz * 100 + (vy + 1) * 10 + (vx + 1);
    }

    unsigned long long acc[8][4];
#pragma unroll
    for (int j = 0; j < 8; ++j)
#pragma unroll
        for (int c = 0; c < 4; ++c) acc[j][c] = 0ull;

    const int nch = Cin / KCH;
    float av[2][KCH];

    // ---- prologue
    __syncthreads();   // zero-fill visible before first STS
    // acts chunk 0: direct load + store
#pragma unroll
    for (int r = 0; r < 2; ++r) {
        if (aok[r]) {
            float4 v = *(const float4*)(asrc[r]);
            av[r][0] = v.x; av[r][1] = v.y; av[r][2] = v.z; av[r][3] = v.w;
        } else { av[r][0] = av[r][1] = av[r][2] = av[r][3] = 0.f; }
#pragma unroll
        for (int kk = 0; kk < KCH; ++kk) xsb0[kk * 400 + ap[r]] = av[r][kk];
    }
    // weights chunk 0 -> stage 0
    for (int i = t; i < 1728; i += 128) {
        int o = i >> 6, r2 = i & 63, kk = r2 >> 4, c4 = r2 & 15;
        cp_async16(wsu0 + (unsigned)i * 16,
                   &w[((size_t)o * Cin + kk) * Cout + co0 + c4 * 4]);
    }
    asm volatile("cp.async.commit_group;" ::: "memory");
    // acts chunk 1 -> regs; weights chunk 1 -> stage 1
#pragma unroll
    for (int r = 0; r < 2; ++r) {
        if (aok[r]) {
            float4 v = *(const float4*)(asrc[r] + KCH);
            av[r][0] = v.x; av[r][1] = v.y; av[r][2] = v.z; av[r][3] = v.w;
        } else { av[r][0] = av[r][1] = av[r][2] = av[r][3] = 0.f; }
    }
    for (int i = t; i < 1728; i += 128) {
        int o = i >> 6, r2 = i & 63, kk = r2 >> 4, c4 = r2 & 15;
        cp_async16(wsu1 + (unsigned)i * 16,
                   &w[((size_t)o * Cin + KCH + kk) * Cout + co0 + c4 * 4]);
    }
    asm volatile("cp.async.commit_group;" ::: "memory");

    // ---- pipelined mainloop
    for (int kc = 0; kc < nch; ++kc) {
        const int s = kc & 1;
        float* xs  = s ? xsb1 : xsb0;
        const float4* ws4 = (const float4*)(s ? wsb1 : wsb0);
        float* xso = s ? xsb0 : xsb1;

        if (kc + 1 < nch) {
            // store acts(kc+1) regs into the other stage
#pragma unroll
            for (int r = 0; r < 2; ++r)
#pragma unroll
                for (int kk = 0; kk < KCH; ++kk) xso[kk * 400 + ap[r]] = av[r][kk];
            // prefetch acts(kc+2) into regs (latency hidden by compute below)
            if (kc + 2 < nch) {
#pragma unroll
                for (int r = 0; r < 2; ++r) {
                    if (aok[r]) {
                        float4 v = *(const float4*)(asrc[r] + (size_t)(kc + 2) * KCH);
                        av[r][0] = v.x; av[r][1] = v.y; av[r][2] = v.z; av[r][3] = v.w;
                    } else { av[r][0] = av[r][1] = av[r][2] = av[r][3] = 0.f; }
                }
            }
            asm volatile("cp.async.wait_group 1;" ::: "memory");
        } else {
            asm volatile("cp.async.wait_group 0;" ::: "memory");
        }
        __syncthreads();

        // ---- compute on stage s (R7 inner loop, unchanged)
#pragma unroll 1
        for (int kk = 0; kk < KCH; ++kk) {
            const float*  xkk = xs + kk * 400;
            const float4* wk4 = ws4 + kk * 16 + cg * 2;
#pragma unroll 1
            for (int dz = 0; dz < 3; ++dz) {
#pragma unroll 1
                for (int dy = 0; dy < 3; ++dy) {
                    const float2* rp2 = (const float2*)(xkk + (zl + dz) * 100 + (gy + dy) * 10);
                    float2 p0 = rp2[0], p1 = rp2[1], p2 = rp2[2], p3 = rp2[3], p4 = rp2[4];
                    unsigned long long rd[10];
                    rd[0] = dup_f32x2(p0.x); rd[1] = dup_f32x2(p0.y);
                    rd[2] = dup_f32x2(p1.x); rd[3] = dup_f32x2(p1.y);
                    rd[4] = dup_f32x2(p2.x); rd[5] = dup_f32x2(p2.y);
                    rd[6] = dup_f32x2(p3.x); rd[7] = dup_f32x2(p3.y);
                    rd[8] = dup_f32x2(p4.x); rd[9] = dup_f32x2(p4.y);
                    const float4* wo4 = wk4 + (size_t)(dz * 9 + dy * 3) * KCH * 16;
#pragma unroll
                    for (int dx = 0; dx < 3; ++dx) {
                        F4U2 b0, b1;
                        b0.f = wo4[(size_t)dx * KCH * 16];
                        b1.f = wo4[(size_t)dx * KCH * 16 + 1];
                        unsigned long long bp0 = b0.u[0], bp1 = b0.u[1];
                        unsigned long long bp2 = b1.u[0], bp3 = b1.u[1];
#pragma unroll
                        for (int j = 0; j < 8; ++j) {
                            unsigned long long a2 = rd[j + dx];
                            fma_f32x2(acc[j][0], a2, bp0);
                            fma_f32x2(acc[j][1], a2, bp1);
                            fma_f32x2(acc[j][2], a2, bp2);
                            fma_f32x2(acc[j][3], a2, bp3);
                        }
                    }
                }
            }
        }

        __syncthreads();
        // issue weights(kc+2) into the stage just freed by this compute
        if (kc + 2 < nch) {
            unsigned int wsu = s ? wsu1 : wsu0;
            for (int i = t; i < 1728; i += 128) {
                int o = i >> 6, r2 = i & 63, kk = r2 >> 4, c4 = r2 & 15;
                cp_async16(wsu + (unsigned)i * 16,
                           &w[((size_t)o * Cin + (kc + 2) * KCH + kk) * Cout + co0 + c4 * 4]);
            }
            asm volatile("cp.async.commit_group;" ::: "memory");
        }
    }

    // ---- epilogue: bias (+residual) (+gelu)
    int co = co0 + cg * 8;
    float bv[8];
#pragma unroll
    for (int c = 0; c < 8; ++c) bv[c] = bias[co + c];
#pragma unroll
    for (int j = 0; j < 8; ++j) {
        int vox = (zbase + zl) * 64 + gy * 8 + j;
        size_t oi = ((size_t)f * VV + vox) * Cout + co;
        float r[8];
#pragma unroll
        for (int c = 0; c < 4; ++c) {
            float lo, hi;
            unpack_f32x2(acc[j][c], lo, hi);
            r[2 * c]     = lo + bv[2 * c];
            r[2 * c + 1] = hi + bv[2 * c + 1];
        }
        if (residual) {
            const float4* rp = (const float4*)(residual + oi);
            float4 r0 = rp[0], r1 = rp[1];
            r[0] += r0.x; r[1] += r0.y; r[2] += r0.z; r[3] += r0.w;
            r[4] += r1.x; r[5] += r1.y; r[6] += r1.z; r[7] += r1.w;
        }
        if (do_gelu) {
#pragma unroll
            for (int c = 0; c < 8; ++c)
                r[c] = 0.5f * r[c] * (1.f + erff(r[c] * 0.7071067811865475f));
        }
        float4* op = (float4*)(y + oi);
        op[0] = make_float4(r[0], r[1], r[2], r[3]);
        op[1] = make_float4(r[4], r[5], r[6], r[7]);
    }
}

// ---------------------------------------------------------------------------
// Attention over time (20 steps) per (b, voxel, head). One warp per unit.
// ---------------------------------------------------------------------------
__global__ void __launch_bounds__(128)
attn_kernel(const float* __restrict__ q, const float* __restrict__ k,
            const float* __restrict__ v, float* __restrict__ o)
{
    __shared__ float sm[4][2380];   // per warp: q 20x33, k 20x33, v 20x33, at 20x20
    int wlocal = threadIdx.x >> 5;
    int lane   = threadIdx.x & 31;
    int wid    = blockIdx.x * 4 + wlocal;     // 0..16383 (B*V*NH)
    int h  = wid & 7;
    int vx = (wid >> 3) & 511;
    int b  = wid >> 12;

    float* qs = sm[wlocal];
    float* ks = qs + 660;
    float* vs = ks + 660;
    float* at = vs + 660;

    size_t base = (size_t)vx * EE + h * HEADD + lane;
#pragma unroll
    for (int s = 0; s < SS; ++s) {
        size_t gi = (size_t)(b * SS + s) * (VV * EE) + base;
        qs[s * 33 + lane] = q[gi];
        ks[s * 33 + lane] = k[gi];
        vs[s * 33 + lane] = v[gi];
    }
    __syncwarp();

    const float scale = 0.17677669529663687f;  // 1/sqrt(32)
    int tt = lane;
#pragma unroll 1
    for (int s = 0; s < SS; ++s) {
        float sc = -1e30f;
        if (tt < SS) {
            float a = 0.f;
#pragma unroll
            for (int d = 0; d < HEADD; ++d)
                a = fmaf(qs[s * 33 + d], ks[tt * 33 + d], a);
            sc = a * scale;
        }
        float m = sc;
#pragma unroll
        for (int off = 16; off > 0; off >>= 1)
            m = fmaxf(m, __shfl_xor_sync(0xffffffffu, m, off));
        float e = (tt < SS) ? expf(sc - m) : 0.f;
        float su = e;
#pragma unroll
        for (int off = 16; off > 0; off >>= 1)
            su += __shfl_xor_sync(0xffffffffu, su, off);
        if (tt < SS) at[s * SS + tt] = e / su;
    }
    __syncwarp();

#pragma unroll 1
    for (int s = 0; s < SS; ++s) {
        float a = 0.f;
#pragma unroll
        for (int t2 = 0; t2 < SS; ++t2)
            a = fmaf(at[s * SS + t2], vs[t2 * 33 + lane], a);
        o[(size_t)(b * SS + s) * (VV * EE) + base] = a;
    }
}

// ---------------------------------------------------------------------------
// Final linear: [40960 x 256] @ [256 x 512] + bias -> logits
// ---------------------------------------------------------------------------
__global__ void __launch_bounds__(256)
linear_kernel(const float* __restrict__ A, const float* __restrict__ Bw,
              const float* __restrict__ bias, float* __restrict__ C)
{
    __shared__ float As[32 * 65];
    __shared__ float Bs[32 * 64];
    int t  = threadIdx.x;
    int tx = t & 15, ty = t >> 4;
    int m0 = blockIdx.x * 64, n0 = blockIdx.y * 64;
    float acc[4][4];
#pragma unroll
    for (int i = 0; i < 4; ++i)
#pragma unroll
        for (int j = 0; j < 4; ++j) acc[i][j] = 0.f;

    for (int kt = 0; kt < 8; ++kt) {
        for (int i = t; i < 2048; i += 256) {
            int r = i >> 5, kk = i & 31;
            As[kk * 65 + r] = A[(size_t)(m0 + r) * EE + kt * 32 + kk];
        }
        for (int i = t; i < 2048; i += 256) {
            int kk = i >> 6, c = i & 63;
            Bs[kk * 64 + c] = Bw[(size_t)(kt * 32 + kk) * NEE + n0 + c];
        }
        __syncthreads();
#pragma unroll
        for (int kk = 0; kk < 32; ++kk) {
            float a[4];
#pragma unroll
            for (int i = 0; i < 4; ++i) a[i] = As[kk * 65 + ty * 4 + i];
            float4 bvv = *(const float4*)&Bs[kk * 64 + tx * 4];
            float bvals[4] = {bvv.x, bvv.y, bvv.z, bvv.w};
#pragma unroll
            for (int i = 0; i < 4; ++i)
#pragma unroll
                for (int j = 0; j < 4; ++j)
                    acc[i][j] = fmaf(a[i], bvals[j], acc[i][j]);
        }
        __syncthreads();
    }
#pragma unroll
    for (int i = 0; i < 4; ++i)
#pragma unroll
        for (int j = 0; j < 4; ++j)
            C[(size_t)(m0 + ty * 4 + i) * NEE + n0 + tx * 4 + j] =
                acc[i][j] + bias[n0 + tx * 4 + j];
}

// ---------------------------------------------------------------------------
// Score transpose: score[b][c][p][v] = logits[b*20+16+p][v][c]
// ---------------------------------------------------------------------------
__global__ void score_kernel(const float* __restrict__ logits, float* __restrict__ out,
                             int out_size)
{
    __shared__ float tile[32][33];
    int bp = blockIdx.z;
    int b = bp >> 2, p = bp & 3;
    int v0 = blockIdx.x * 32, c0 = blockIdx.y * 32;
    int f = b * SS + BPTT + p;
    int t = threadIdx.x;
    int ci = t & 31, vi = t >> 5;     // vi 0..7
#pragma unroll
    for (int r = 0; r < 32; r += 8)
        tile[vi + r][ci] = logits[((size_t)f * VV + v0 + vi + r) * NEE + c0 + ci];
    __syncthreads();
    int vv2 = t & 31, cc = t >> 5;
#pragma unroll
    for (int r = 0; r < 32; r += 8) {
        size_t oidx = (((size_t)(b * NEE + c0 + cc + r)) * PRED + p) * VV + v0 + vv2;
        if (oidx < (size_t)out_size) out[oidx] = tile[vv2][cc + r];
    }
}

// ---------------------------------------------------------------------------
// Per-row log-softmax target loss + argmax. Warp per (b,p,v) row.
// ---------------------------------------------------------------------------
__global__ void loss_argmax_kernel(const float* __restrict__ logits,
                                   const int* __restrict__ ncode,
                                   float* __restrict__ rowloss,
                                   float* __restrict__ out, int write_code)
{
    int wid  = (int)((blockIdx.x * blockDim.x + threadIdx.x) >> 5);
    int lane = threadIdx.x & 31;
    if (wid >= NROWS) return;
    int v = wid & 511, p = (wid >> 9) & 3, b = wid >> 11;
    const float* lp = logits + ((size_t)(b * SS + BPTT + p) * VV + v) * NEE;

    float vals[16];
    float mx = -1e30f;
    int mi = 0;
#pragma unroll
    for (int i = 0; i < 16; ++i) {
        int c = lane + i * 32;
        float xv = lp[c];
        vals[i] = xv;
        if (xv > mx) { mx = xv; mi = c; }
    }
#pragma unroll
    for (int off = 16; off > 0; off >>= 1) {
        float om = __shfl_xor_sync(0xffffffffu, mx, off);
        int   oi = __shfl_xor_sync(0xffffffffu, mi, off);
        if (om > mx || (om == mx && oi < mi)) { mx = om; mi = oi; }
    }
    float se = 0.f;
#pragma unroll
    for (int i = 0; i < 16; ++i) se += expf(vals[i] - mx);
#pragma unroll
    for (int off = 16; off > 0; off >>= 1)
        se += __shfl_xor_sync(0xffffffffu, se, off);

    int tgt = ncode[wid];
    if (lane == (tgt & 31))
        rowloss[wid] = -(vals[tgt >> 5] - mx - logf(se));
    if (write_code && lane == 0)
        out[(size_t)SCORE_SIZE + 1 + wid] = (float)mi;
}

__global__ void loss_reduce_kernel(const float* __restrict__ rowloss,
                                   float* __restrict__ out, int loss_off)
{
    __shared__ float smr[256];
    int t = threadIdx.x;
    float a = 0.f;
    for (int i = t; i < NROWS; i += 256) a += rowloss[i];
    smr[t] = a;
    __syncthreads();
    for (int s = 128; s > 0; s >>= 1) {
        if (t < s) smr[t] += smr[t + s];
        __syncthreads();
    }
    if (t == 0) out[loss_off] = smr[0] * (1.f / (float)NROWS);
}

// ---------------------------------------------------------------------------
// Orchestration
// ---------------------------------------------------------------------------
extern "C" void kernel_launch(void* const* d_in, const int* in_sizes, int n_in,
                              void* d_out, int out_size)
{
    (void)in_sizes; (void)n_in;
    const int*   code   = (const int*)  d_in[0];
    const int*   ncode  = (const int*)  d_in[1];
    const float* emb    = (const float*)d_in[2];
    const float* pos    = (const float*)d_in[3];
    const float* ln1s   = (const float*)d_in[4];
    const float* ln1b   = (const float*)d_in[5];
    const float* ln2s   = (const float*)d_in[6];
    const float* ln2b   = (const float*)d_in[7];
    const float* wq     = (const float*)d_in[8];
    const float* bq     = (const float*)d_in[9];
    const float* wk     = (const float*)d_in[10];
    const float* bk     = (const float*)d_in[11];
    const float* wv     = (const float*)d_in[12];
    const float* bv     = (const float*)d_in[13];
    const float* wo     = (const float*)d_in[14];
    const float* bo     = (const float*)d_in[15];
    const float* w1     = (const float*)d_in[16];
    const float* b1     = (const float*)d_in[17];
    const float* w2     = (const float*)d_in[18];
    const float* b2     = (const float*)d_in[19];
    const float* lnfs   = (const float*)d_in[20];
    const float* lnfb   = (const float*)d_in[21];
    const float* decw   = (const float*)d_in[22];
    const float* decb   = (const float*)d_in[23];
    const float* declns = (const float*)d_in[24];
    const float* declnb = (const float*)d_in[25];
    const float* linw   = (const float*)d_in[26];
    const float* linb   = (const float*)d_in[27];
    float* out = (float*)d_out;

    float *px, *ph, *pq, *pk, *pv, *pa, *phid, *plog, *prl;
    cudaGetSymbolAddress((void**)&px,   g_x);
    cudaGetSymbolAddress((void**)&ph,   g_h);
    cudaGetSymbolAddress((void**)&pq,   g_q);
    cudaGetSymbolAddress((void**)&pk,   g_k);
    cudaGetSymbolAddress((void**)&pv,   g_v);
    cudaGetSymbolAddress((void**)&pa,   g_ao);
    cudaGetSymbolAddress((void**)&phid, g_hid);
    cudaGetSymbolAddress((void**)&plog, g_logits);
    cudaGetSymbolAddress((void**)&prl,  g_rowloss);

    cudaFuncSetAttribute(conv3d_kernel,
                         cudaFuncAttributeMaxDynamicSharedMemorySize,
                         CONV_SMEM_BYTES);

    const int ROWS = FF * VV;                  // 40960
    const int LN_BLOCKS = (ROWS * 32) / 256;   // 5120
    const size_t WEE = 27 * 256 * 256;         // per-layer E->E weight stride
    const size_t WEH = 27 * 256 * 512;         // per-layer E->HID (== HID->E)

    embed_kernel<<<(int)((FVE + 255) / 256), 256>>>(code, emb, pos, px);

    dim3 cgE(FF, 4, 4);   // Cout=256
    dim3 cgH(FF, 8, 4);   // Cout=512
    for (int i = 0; i < 4; ++i) {
        ln_kernel<<<LN_BLOCKS, 256>>>(px, ph, ln1s + i * EE, ln1b + i * EE, ROWS);
        conv3d_kernel<<<cgE, 128, CONV_SMEM_BYTES>>>(ph, wq + i * WEE, bq + i * EE, nullptr, pq, 256, 256, 0);
        conv3d_kernel<<<cgE, 128, CONV_SMEM_BYTES>>>(ph, wk + i * WEE, bk + i * EE, nullptr, pk, 256, 256, 0);
        conv3d_kernel<<<cgE, 128, CONV_SMEM_BYTES>>>(ph, wv + i * WEE, bv + i * EE, nullptr, pv, 256, 256, 0);
        attn_kernel<<<4096, 128>>>(pq, pk, pv, pa);
        conv3d_kernel<<<cgE, 128, CONV_SMEM_BYTES>>>(pa, wo + i * WEE, bo + i * EE, px, px, 256, 256, 0);
        ln_kernel<<<LN_BLOCKS, 256>>>(px, ph, ln2s + i * EE, ln2b + i * EE, ROWS);
        conv3d_kernel<<<cgH, 128, CONV_SMEM_BYTES>>>(ph, w1 + i * WEH, b1 + i * HIDD, nullptr, phid, 256, 512, 1);
        conv3d_kernel<<<cgE, 128, CONV_SMEM_BYTES>>>(phid, w2 + i * WEH, b2 + i * EE, px, px, 512, 256, 0);
    }

    ln_kernel<<<LN_BLOCKS, 256>>>(px, ph, lnfs, lnfb, ROWS);
    conv3d_kernel<<<cgE, 128, CONV_SMEM_BYTES>>>(ph, decw, decb, nullptr, pq, 256, 256, 1);
    ln_kernel<<<LN_BLOCKS, 256>>>(pq, pk, declns, declnb, ROWS);
    linear_kernel<<<dim3(ROWS / 64, NEE / 64), 256>>>(pk, linw, linb, plog);

    if (out_size >= SCORE_SIZE) {
        dim3 sg(16, 16, 16);
        score_kernel<<<sg, 256>>>(plog, out, out_size);
    }
    int write_code = (out_size >= SCORE_SIZE + 1 + NROWS) ? 1 : 0;
    loss_argmax_kernel<<<(NROWS * 32) / 256, 256>>>(plog, ncode, prl, out, write_code);

    int loss_off = -1;
    if (out_size == 1) loss_off = 0;
    else if (out_size > SCORE_SIZE) loss_off = SCORE_SIZE;
    if (loss_off >= 0)
        loss_reduce_kernel<<<1, 256>>>(prl, out, loss_off);
}

// round 14
// speedup vs baseline: 1.8694x; 1.5311x over previous
#include <cuda_runtime.h>
#include <cuda_fp16.h>
#include <math.h>

// ---------------------------------------------------------------------------
// Problem constants
// ---------------------------------------------------------------------------
#define BB    4
#define BPTT  16
#define PRED  4
#define SS    20
#define VV    512
#define EE    256
#define NHH   8
#define HEADD 32
#define HIDD  512
#define NEE   512
#define FF    80

#define FVE   ((size_t)FF * VV * EE)
#define FVH   ((size_t)FF * VV * HIDD)
#define SCORE_SIZE (BB * NEE * PRED * VV)
#define NROWS (BB * PRED * VV)

#define WEE27 1769472ull                 // 27*256*256
#define WEH27 3538944ull                 // 27*256*512
#define WT_LAYER (4ull*WEE27 + 2ull*WEH27)
#define WT_TOTAL (4ull*WT_LAYER + WEE27)

// ---------------------------------------------------------------------------
// Scratch (allocation-free: __device__ globals)
// ---------------------------------------------------------------------------
__device__ float g_x[FVE];
__device__ float g_q[FVE];
__device__ float g_k[FVE];
__device__ float g_v[FVE];
__device__ float g_logits[FVH];
__device__ float g_rowloss[NROWS];
__device__ __half g_ah[FVE];
__device__ __half g_al[FVE];
__device__ __half g_bh[FVH];
__device__ __half g_bl[FVH];
__device__ __half g_wth[WT_TOTAL];
__device__ __half g_wtl[WT_TOTAL];

// ---------------------------------------------------------------------------
// PTX helpers (baseline sm_103-compatible: cp.async, ldmatrix, mma.sync)
// ---------------------------------------------------------------------------
__device__ __forceinline__ unsigned smem_u32(const void* p) {
    unsigned a;
    asm("{ .reg .u64 t; cvta.to.shared.u64 t, %1; cvt.u32.u64 %0, t; }"
        : "=r"(a) : "l"(p));
    return a;
}
__device__ __forceinline__ void cp_async16z(unsigned dst, const void* src, int ssz) {
    asm volatile("cp.async.cg.shared.global [%0], [%1], 16, %2;"
                 :: "r"(dst), "l"(src), "r"(ssz) : "memory");
}
__device__ __forceinline__ void ldsm4(unsigned* r, unsigned addr) {
    asm volatile("ldmatrix.sync.aligned.m8n8.x4.shared.b16 {%0,%1,%2,%3}, [%4];"
                 : "=r"(r[0]), "=r"(r[1]), "=r"(r[2]), "=r"(r[3]) : "r"(addr));
}
__device__ __forceinline__ void mma16816(float* d, const unsigned* a, const unsigned* b) {
    asm volatile(
        "mma.sync.aligned.m16n8k16.row.col.f32.f16.f16.f32 "
        "{%0,%1,%2,%3}, {%4,%5,%6,%7}, {%8,%9}, {%0,%1,%2,%3};"
        : "+f"(d[0]), "+f"(d[1]), "+f"(d[2]), "+f"(d[3])
        : "r"(a[0]), "r"(a[1]), "r"(a[2]), "r"(a[3]), "r"(b[0]), "r"(b[1]));
}

// ---------------------------------------------------------------------------
// Weight transpose + fp16 split:  w[27][Cin][Cout] f32 -> wt[27][Cout][Cin] hi/lo
// ---------------------------------------------------------------------------
__global__ void wconv_kernel(const float* __restrict__ w,
                             __half* __restrict__ th,
                             __half* __restrict__ tl,
                             int Cin, int Cout)
{
    size_t n = (size_t)27 * Cin * Cout;
    size_t i = (size_t)blockIdx.x * 256 + threadIdx.x;
    if (i >= n) return;
    int pc = Cin * Cout;
    int o = (int)(i / pc);
    int r = (int)(i - (size_t)o * pc);
    int co = r / Cin, ci = r - co * Cin;
    float x = w[((size_t)o * Cin + ci) * Cout + co];
    __half h = __float2half(x);
    th[i] = h;
    tl[i] = __float2half(x - __half2float(h));
}

// ---------------------------------------------------------------------------
// Embedding
// ---------------------------------------------------------------------------
__global__ void embed_kernel(const int* __restrict__ code,
                             const float* __restrict__ emb,
                             const float* __restrict__ pos,
                             float* __restrict__ x)
{
    size_t idx = (size_t)blockIdx.x * blockDim.x + threadIdx.x;
    if (idx >= FVE) return;
    int e = (int)(idx & 255);
    int v = (int)((idx >> 8) & 511);
    int f = (int)(idx >> 17);
    int b = f / SS, s = f % SS;
    int tok = (s < BPTT) ? code[((b * BPTT + s) << 9) + v] : NEE;
    x[idx] = emb[tok * EE + e] + pos[s * EE + e];
}

// ---------------------------------------------------------------------------
// LayerNorm; writes f32 and/or fp16 hi/lo pair
// ---------------------------------------------------------------------------
__global__ void ln_kernel(const float* __restrict__ in,
                          float* __restrict__ outF,
                          __half* __restrict__ outH,
                          __half* __restrict__ outL,
                          const float* __restrict__ sc, const float* __restrict__ bi,
                          int rows)
{
    int wid  = (int)((blockIdx.x * blockDim.x + threadIdx.x) >> 5);
    int lane = threadIdx.x & 31;
    if (wid >= rows) return;
    const float* p = in + (size_t)wid * EE;
    float v8[8];
    float s = 0.f, sq = 0.f;
#pragma unroll
    for (int i = 0; i < 8; ++i) {
        float xv = p[lane + i * 32];
        v8[i] = xv; s += xv; sq = fmaf(xv, xv, sq);
    }
#pragma unroll
    for (int off = 16; off > 0; off >>= 1) {
        s  += __shfl_xor_sync(0xffffffffu, s, off);
        sq += __shfl_xor_sync(0xffffffffu, sq, off);
    }
    float m   = s * (1.f / 256.f);
    float var = sq * (1.f / 256.f) - m * m;
    if (var < 0.f) var = 0.f;
    float inv = rsqrtf(var + 1e-5f);
#pragma unroll
    for (int i = 0; i < 8; ++i) {
        int e = lane + i * 32;
        float r = (v8[i] - m) * inv * sc[e] + bi[e];
        size_t oi = (size_t)wid * EE + e;
        if (outF) outF[oi] = r;
        if (outH) {
            __half h = __float2half(r);
            outH[oi] = h;
            outL[oi] = __float2half(r - __half2float(h));
        }
    }
}

// ---------------------------------------------------------------------------
// Tensor-core (mma.sync fp16) 3D conv, 3x3x3 SAME, fp16x3 split precision,
// with PER-CHUNK ACCUMULATOR DRAIN: mma.sync f32 accumulation truncates (RZ);
// draining acc into a master register set with IEEE-RN FADD each chunk bounds
// the bias to ~sqrt(1/nchunks) of the undrained value.
//   CTA: 256 thr (8 warps), tile M=128 x N=64; warp tile 32x32.
//   K loop = 27 taps x Cin/64 chunks.
// ---------------------------------------------------------------------------
#define APAD 144                           // bytes per smem row (72 halves)
#define AH_OFF 0
#define AL_OFF (128 * APAD)                // 18432
#define BH_OFF (2 * 128 * APAD)            // 36864
#define BL_OFF (BH_OFF + 64 * APAD)        // 46080
#define TC_SMEM_BYTES (BL_OFF + 64 * APAD) // 55296

__global__ void __launch_bounds__(256, 2)
conv3d_mma_kernel(const __half* __restrict__ xh,
                  const __half* __restrict__ xl,
                  const __half* __restrict__ wth,
                  const __half* __restrict__ wtl,
                  const float* __restrict__ bias, const float* __restrict__ residual,
                  float* __restrict__ yf,
                  __half* __restrict__ yh, __half* __restrict__ yl,
                  int Cin, int Cout, int do_gelu)
{
    extern __shared__ char smem[];
    unsigned sb = smem_u32(smem);
    const int t = threadIdx.x, w = t >> 5, lane = t & 31;
    const int wm = w & 3, wn = w >> 2;      // warp covers rows wm*32, cols wn*32
    const int f = blockIdx.x, co0 = blockIdx.y * 64, v0 = blockIdx.z * 128;

    // A staging: thread t -> tile row t/2, 32-half part t&1
    const int arow = t >> 1, apart = t & 1;
    const int av = v0 + arow, vz = av >> 6, vy = (av >> 3) & 7, vx = av & 7;
    // B staging: thread t -> cout row t/4, quads (t&3)*2..+1
    const int brow = t >> 2, bq0 = (t & 3) * 2;

    float acc[2][4][4], mst[2][4][4];
#pragma unroll
    for (int mt = 0; mt < 2; ++mt)
#pragma unroll
        for (int nt = 0; nt < 4; ++nt)
#pragma unroll
            for (int q = 0; q < 4; ++q) { acc[mt][nt][q] = 0.f; mst[mt][nt][q] = 0.f; }

    // ldmatrix lane base addresses
    const int rA = ((lane >> 3) & 1) * 8 + (lane & 7);
    const int cA = (lane >> 4) * 16;
    unsigned aAh[2], aAl[2];
#pragma unroll
    for (int mt = 0; mt < 2; ++mt) {
        unsigned off = (unsigned)(wm * 32 + mt * 16 + rA) * APAD + cA;
        aAh[mt] = sb + AH_OFF + off;
        aAl[mt] = sb + AL_OFF + off;
    }
    const int rB = ((lane >> 4) & 1) * 8 + (lane & 7);
    const int cB = ((lane >> 3) & 1) * 16;
    unsigned aBh[2], aBl[2];
#pragma unroll
    for (int nt2 = 0; nt2 < 2; ++nt2) {
        unsigned off = (unsigned)(wn * 32 + nt2 * 16 + rB) * APAD + cB;
        aBh[nt2] = sb + BH_OFF + off;
        aBl[nt2] = sb + BL_OFF + off;
    }

    const int ncc = Cin >> 6;
    const int nchunks = 27 * ncc;

    for (int ch = 0; ch < nchunks; ++ch) {
        int o = ch / ncc, c = ch - o * ncc;
        int dz = o / 9 - 1, dy = (o % 9) / 3 - 1, dx = o % 3 - 1;

        __syncthreads();   // previous compute done before overwriting smem

        // ---- stage A (hi+lo): row arow = shifted voxel, 4x16B per part, zero-fill OOB
        int zz = vz + dz, yy = vy + dy, xx = vx + dx;
        int ok = ((unsigned)zz < 8u) && ((unsigned)yy < 8u) && ((unsigned)xx < 8u);
        size_t abase = ((size_t)f * VV + (size_t)(zz * 64 + yy * 8 + xx)) * Cin
                       + (size_t)c * 64 + apart * 32;
        const __half* sah = ok ? (xh + abase) : xh;
        const __half* sal = ok ? (xl + abase) : xl;
        int ssz = ok ? 16 : 0;
        unsigned dah = sb + AH_OFF + (unsigned)arow * APAD + apart * 64;
        unsigned dal = sb + AL_OFF + (unsigned)arow * APAD + apart * 64;
#pragma unroll
        for (int i = 0; i < 4; ++i) {
            cp_async16z(dah + i * 16, sah + i * 8, ssz);
            cp_async16z(dal + i * 16, sal + i * 8, ssz);
        }
        // ---- stage B (hi+lo): row = cout (Cin-major contiguous)
        size_t bbase = ((size_t)o * Cout + (size_t)(co0 + brow)) * Cin + (size_t)c * 64;
        unsigned dbh = sb + BH_OFF + (unsigned)brow * APAD;
        unsigned dbl = sb + BL_OFF + (unsigned)brow * APAD;
#pragma unroll
        for (int q2 = 0; q2 < 2; ++q2) {
            int i = bq0 + q2;
            cp_async16z(dbh + i * 16, wth + bbase + i * 8, 16);
            cp_async16z(dbl + i * 16, wtl + bbase + i * 8, 16);
        }
        asm volatile("cp.async.commit_group;" ::: "memory");
        asm volatile("cp.async.wait_group 0;" ::: "memory");
        __syncthreads();

        // ---- compute: 4 k16 steps x (2 mt x 4 nt) x 3 terms
#pragma unroll
        for (int ks = 0; ks < 4; ++ks) {
            unsigned kb = (unsigned)ks * 32;
            unsigned fAh[2][4], fAl[2][4], fBh[4][2], fBl[4][2];
#pragma unroll
            for (int mt = 0; mt < 2; ++mt) {
                ldsm4(fAh[mt], aAh[mt] + kb);
                ldsm4(fAl[mt], aAl[mt] + kb);
            }
#pragma unroll
            for (int nt2 = 0; nt2 < 2; ++nt2) {
                unsigned r4[4];
                ldsm4(r4, aBh[nt2] + kb);
                fBh[nt2 * 2][0] = r4[0]; fBh[nt2 * 2][1] = r4[1];
                fBh[nt2 * 2 + 1][0] = r4[2]; fBh[nt2 * 2 + 1][1] = r4[3];
                ldsm4(r4, aBl[nt2] + kb);
                fBl[nt2 * 2][0] = r4[0]; fBl[nt2 * 2][1] = r4[1];
                fBl[nt2 * 2 + 1][0] = r4[2]; fBl[nt2 * 2 + 1][1] = r4[3];
            }
#pragma unroll
            for (int mt = 0; mt < 2; ++mt)
#pragma unroll
                for (int nt = 0; nt < 4; ++nt) {
                    mma16816(acc[mt][nt], fAh[mt], fBh[nt]);
                    mma16816(acc[mt][nt], fAl[mt], fBh[nt]);
                    mma16816(acc[mt][nt], fAh[mt], fBl[nt]);
                }
        }
        // ---- drain: RN-add chunk partial into master, reset acc (bounds RZ bias)
#pragma unroll
        for (int mt = 0; mt < 2; ++mt)
#pragma unroll
            for (int nt = 0; nt < 4; ++nt)
#pragma unroll
                for (int q = 0; q < 4; ++q) {
                    mst[mt][nt][q] += acc[mt][nt][q];
                    acc[mt][nt][q] = 0.f;
                }
    }

    // ---- epilogue: D frag lane map: d0,d1 = (m=lane/4, n=2*(lane%4)+0,1);
    //               d2,d3 = (m=lane/4+8, same n)
    const int mrow0 = wm * 32 + (lane >> 2);
    const int ncol0 = (lane & 3) * 2;
#pragma unroll
    for (int mt = 0; mt < 2; ++mt)
#pragma unroll
        for (int half = 0; half < 2; ++half) {
            int m = mrow0 + mt * 16 + half * 8;
            int v = v0 + m;
            size_t rowbase = ((size_t)f * VV + v) * Cout;
#pragma unroll
            for (int nt = 0; nt < 4; ++nt) {
                int col = co0 + wn * 32 + nt * 8 + ncol0;
                size_t oi = rowbase + col;
                float r0 = mst[mt][nt][half * 2 + 0] + bias[col];
                float r1 = mst[mt][nt][half * 2 + 1] + bias[col + 1];
                if (residual) { r0 += residual[oi]; r1 += residual[oi + 1]; }
                if (do_gelu) {
                    r0 = 0.5f * r0 * (1.f + erff(r0 * 0.7071067811865475f));
                    r1 = 0.5f * r1 * (1.f + erff(r1 * 0.7071067811865475f));
                }
                if (yf) { yf[oi] = r0; yf[oi + 1] = r1; }
                if (yh) {
                    __half h0 = __float2half(r0);
                    __half h1 = __float2half(r1);
                    yh[oi] = h0; yh[oi + 1] = h1;
                    yl[oi]     = __float2half(r0 - __half2float(h0));
                    yl[oi + 1] = __float2half(r1 - __half2float(h1));
                }
            }
        }
}

// ---------------------------------------------------------------------------
// Attention over time (20 steps) per (b, voxel, head). Writes fp16 hi/lo.
// ---------------------------------------------------------------------------
__global__ void __launch_bounds__(128)
attn_kernel(const float* __restrict__ q, const float* __restrict__ k,
            const float* __restrict__ v,
            __half* __restrict__ oh, __half* __restrict__ ol)
{
    __shared__ float sm[4][2380];
    int wlocal = threadIdx.x >> 5;
    int lane   = threadIdx.x & 31;
    int wid    = blockIdx.x * 4 + wlocal;
    int h  = wid & 7;
    int vx = (wid >> 3) & 511;
    int b  = wid >> 12;

    float* qs = sm[wlocal];
    float* ks = qs + 660;
    float* vs = ks + 660;
    float* at = vs + 660;

    size_t base = (size_t)vx * EE + h * HEADD + lane;
#pragma unroll
    for (int s = 0; s < SS; ++s) {
        size_t gi = (size_t)(b * SS + s) * (VV * EE) + base;
        qs[s * 33 + lane] = q[gi];
        ks[s * 33 + lane] = k[gi];
        vs[s * 33 + lane] = v[gi];
    }
    __syncwarp();

    const float scale = 0.17677669529663687f;
    int tt = lane;
#pragma unroll 1
    for (int s = 0; s < SS; ++s) {
        float sc = -1e30f;
        if (tt < SS) {
            float a = 0.f;
#pragma unroll
            for (int d = 0; d < HEADD; ++d)
                a = fmaf(qs[s * 33 + d], ks[tt * 33 + d], a);
            sc = a * scale;
        }
        float m = sc;
#pragma unroll
        for (int off = 16; off > 0; off >>= 1)
            m = fmaxf(m, __shfl_xor_sync(0xffffffffu, m, off));
        float e = (tt < SS) ? expf(sc - m) : 0.f;
        float su = e;
#pragma unroll
        for (int off = 16; off > 0; off >>= 1)
            su += __shfl_xor_sync(0xffffffffu, su, off);
        if (tt < SS) at[s * SS + tt] = e / su;
    }
    __syncwarp();

#pragma unroll 1
    for (int s = 0; s < SS; ++s) {
        float a = 0.f;
#pragma unroll
        for (int t2 = 0; t2 < SS; ++t2)
            a = fmaf(at[s * SS + t2], vs[t2 * 33 + lane], a);
        size_t gi = (size_t)(b * SS + s) * (VV * EE) + base;
        __half hb = __float2half(a);
        oh[gi] = hb;
        ol[gi] = __float2half(a - __half2float(hb));
    }
}

// ---------------------------------------------------------------------------
// Final linear: [40960 x 256] @ [256 x 512] + bias
// ---------------------------------------------------------------------------
__global__ void __launch_bounds__(256)
linear_kernel(const float* __restrict__ A, const float* __restrict__ Bw,
              const float* __restrict__ bias, float* __restrict__ C)
{
    __shared__ float As[32 * 65];
    __shared__ float Bs[32 * 64];
    int t  = threadIdx.x;
    int tx = t & 15, ty = t >> 4;
    int m0 = blockIdx.x * 64, n0 = blockIdx.y * 64;
    float acc[4][4];
#pragma unroll
    for (int i = 0; i < 4; ++i)
#pragma unroll
        for (int j = 0; j < 4; ++j) acc[i][j] = 0.f;

    for (int kt = 0; kt < 8; ++kt) {
        for (int i = t; i < 2048; i += 256) {
            int r = i >> 5, kk = i & 31;
            As[kk * 65 + r] = A[(size_t)(m0 + r) * EE + kt * 32 + kk];
        }
        for (int i = t; i < 2048; i += 256) {
            int kk = i >> 6, c = i & 63;
            Bs[kk * 64 + c] = Bw[(size_t)(kt * 32 + kk) * NEE + n0 + c];
        }
        __syncthreads();
#pragma unroll
        for (int kk = 0; kk < 32; ++kk) {
            float a[4];
#pragma unroll
            for (int i = 0; i < 4; ++i) a[i] = As[kk * 65 + ty * 4 + i];
            float4 bvv = *(const float4*)&Bs[kk * 64 + tx * 4];
            float bvals[4] = {bvv.x, bvv.y, bvv.z, bvv.w};
#pragma unroll
            for (int i = 0; i < 4; ++i)
#pragma unroll
                for (int j = 0; j < 4; ++j)
                    acc[i][j] = fmaf(a[i], bvals[j], acc[i][j]);
        }
        __syncthreads();
    }
#pragma unroll
    for (int i = 0; i < 4; ++i)
#pragma unroll
        for (int j = 0; j < 4; ++j)
            C[(size_t)(m0 + ty * 4 + i) * NEE + n0 + tx * 4 + j] =
                acc[i][j] + bias[n0 + tx * 4 + j];
}

// ---------------------------------------------------------------------------
// Score transpose
// ---------------------------------------------------------------------------
__global__ void score_kernel(const float* __restrict__ logits, float* __restrict__ out,
                             int out_size)
{
    __shared__ float tile[32][33];
    int bp = blockIdx.z;
    int b = bp >> 2, p = bp & 3;
    int v0 = blockIdx.x * 32, c0 = blockIdx.y * 32;
    int f = b * SS + BPTT + p;
    int t = threadIdx.x;
    int ci = t & 31, vi = t >> 5;
#pragma unroll
    for (int r = 0; r < 32; r += 8)
        tile[vi + r][ci] = logits[((size_t)f * VV + v0 + vi + r) * NEE + c0 + ci];
    __syncthreads();
    int vv2 = t & 31, cc = t >> 5;
#pragma unroll
    for (int r = 0; r < 32; r += 8) {
        size_t oidx = (((size_t)(b * NEE + c0 + cc + r)) * PRED + p) * VV + v0 + vv2;
        if (oidx < (size_t)out_size) out[oidx] = tile[vv2][cc + r];
    }
}

// ---------------------------------------------------------------------------
// Loss + argmax
// ---------------------------------------------------------------------------
__global__ void loss_argmax_kernel(const float* __restrict__ logits,
                                   const int* __restrict__ ncode,
                                   float* __restrict__ rowloss,
                                   float* __restrict__ out, int write_code)
{
    int wid  = (int)((blockIdx.x * blockDim.x + threadIdx.x) >> 5);
    int lane = threadIdx.x & 31;
    if (wid >= NROWS) return;
    int v = wid & 511, p = (wid >> 9) & 3, b = wid >> 11;
    const float* lp = logits + ((size_t)(b * SS + BPTT + p) * VV + v) * NEE;

    float vals[16];
    float mx = -1e30f;
    int mi = 0;
#pragma unroll
    for (int i = 0; i < 16; ++i) {
        int c = lane + i * 32;
        float xv = lp[c];
        vals[i] = xv;
        if (xv > mx) { mx = xv; mi = c; }
    }
#pragma unroll
    for (int off = 16; off > 0; off >>= 1) {
        float om = __shfl_xor_sync(0xffffffffu, mx, off);
        int   oi = __shfl_xor_sync(0xffffffffu, mi, off);
        if (om > mx || (om == mx && oi < mi)) { mx = om; mi = oi; }
    }
    float se = 0.f;
#pragma unroll
    for (int i = 0; i < 16; ++i) se += expf(vals[i] - mx);
#pragma unroll
    for (int off = 16; off > 0; off >>= 1)
        se += __shfl_xor_sync(0xffffffffu, se, off);

    int tgt = ncode[wid];
    if (lane == (tgt & 31))
        rowloss[wid] = -(vals[tgt >> 5] - mx - logf(se));
    if (write_code && lane == 0)
        out[(size_t)SCORE_SIZE + 1 + wid] = (float)mi;
}

__global__ void loss_reduce_kernel(const float* __restrict__ rowloss,
                                   float* __restrict__ out, int loss_off)
{
    __shared__ float smr[256];
    int t = threadIdx.x;
    float a = 0.f;
    for (int i = t; i < NROWS; i += 256) a += rowloss[i];
    smr[t] = a;
    __syncthreads();
    for (int s = 128; s > 0; s >>= 1) {
        if (t < s) smr[t] += smr[t + s];
        __syncthreads();
    }
    if (t == 0) out[loss_off] = smr[0] * (1.f / (float)NROWS);
}

// ---------------------------------------------------------------------------
// Orchestration
// ---------------------------------------------------------------------------
extern "C" void kernel_launch(void* const* d_in, const int* in_sizes, int n_in,
                              void* d_out, int out_size)
{
    (void)in_sizes; (void)n_in;
    const int*   code   = (const int*)  d_in[0];
    const int*   ncode  = (const int*)  d_in[1];
    const float* emb    = (const float*)d_in[2];
    const float* pos    = (const float*)d_in[3];
    const float* ln1s   = (const float*)d_in[4];
    const float* ln1b   = (const float*)d_in[5];
    const float* ln2s   = (const float*)d_in[6];
    const float* ln2b   = (const float*)d_in[7];
    const float* wq     = (const float*)d_in[8];
    const float* bq     = (const float*)d_in[9];
    const float* wk     = (const float*)d_in[10];
    const float* bk     = (const float*)d_in[11];
    const float* wv     = (const float*)d_in[12];
    const float* bv     = (const float*)d_in[13];
    const float* wo     = (const float*)d_in[14];
    const float* bo     = (const float*)d_in[15];
    const float* w1     = (const float*)d_in[16];
    const float* b1     = (const float*)d_in[17];
    const float* w2     = (const float*)d_in[18];
    const float* b2     = (const float*)d_in[19];
    const float* lnfs   = (const float*)d_in[20];
    const float* lnfb   = (const float*)d_in[21];
    const float* decw   = (const float*)d_in[22];
    const float* decb   = (const float*)d_in[23];
    const float* declns = (const float*)d_in[24];
    const float* declnb = (const float*)d_in[25];
    const float* linw   = (const float*)d_in[26];
    const float* linb   = (const float*)d_in[27];
    float* out = (float*)d_out;

    float *px, *pq, *pk, *pv, *plog, *prl;
    __half *pah, *pal, *pbh, *pbl, *pwh, *pwl;
    cudaGetSymbolAddress((void**)&px,   g_x);
    cudaGetSymbolAddress((void**)&pq,   g_q);
    cudaGetSymbolAddress((void**)&pk,   g_k);
    cudaGetSymbolAddress((void**)&pv,   g_v);
    cudaGetSymbolAddress((void**)&plog, g_logits);
    cudaGetSymbolAddress((void**)&prl,  g_rowloss);
    cudaGetSymbolAddress((void**)&pah,  g_ah);
    cudaGetSymbolAddress((void**)&pal,  g_al);
    cudaGetSymbolAddress((void**)&pbh,  g_bh);
    cudaGetSymbolAddress((void**)&pbl,  g_bl);
    cudaGetSymbolAddress((void**)&pwh,  g_wth);
    cudaGetSymbolAddress((void**)&pwl,  g_wtl);

    cudaFuncSetAttribute(conv3d_mma_kernel,
                         cudaFuncAttributeMaxDynamicSharedMemorySize,
                         TC_SMEM_BYTES);

    const int ROWS = FF * VV;
    const int LN_BLOCKS = (ROWS * 32) / 256;
    const size_t WEE = 27 * 256 * 256;
    const size_t WEH = 27 * 256 * 512;

    // ---- convert + transpose all conv weights to fp16 hi/lo ----
    auto wcv = [&](const float* w, size_t off, int Cin, int Cout) {
        size_t n = (size_t)27 * Cin * Cout;
        wconv_kernel<<<(unsigned)((n + 255) / 256), 256>>>(w, pwh + off, pwl + off, Cin, Cout);
    };
    for (int i = 0; i < 4; ++i) {
        size_t base = (size_t)i * WT_LAYER;
        wcv(wq + i * WEE, base + 0 * WEE27, 256, 256);
        wcv(wk + i * WEE, base + 1 * WEE27, 256, 256);
        wcv(wv + i * WEE, base + 2 * WEE27, 256, 256);
        wcv(wo + i * WEE, base + 3 * WEE27, 256, 256);
        wcv(w1 + i * WEH, base + 4 * WEE27, 256, 512);
        wcv(w2 + i * WEH, base + 4 * WEE27 + WEH27, 512, 256);
    }
    const size_t offdec = 4 * WT_LAYER;
    wcv(decw, offdec, 256, 256);

    embed_kernel<<<(int)((FVE + 255) / 256), 256>>>(code, emb, pos, px);

    dim3 cgE(FF, 4, 4);   // Cout=256
    dim3 cgH(FF, 8, 4);   // Cout=512
    for (int i = 0; i < 4; ++i) {
        size_t base = (size_t)i * WT_LAYER;
        ln_kernel<<<LN_BLOCKS, 256>>>(px, nullptr, pah, pal,
                                      ln1s + i * EE, ln1b + i * EE, ROWS);
        conv3d_mma_kernel<<<cgE, 256, TC_SMEM_BYTES>>>(pah, pal,
            pwh + base + 0 * WEE27, pwl + base + 0 * WEE27,
            bq + i * EE, nullptr, pq, nullptr, nullptr, 256, 256, 0);
        conv3d_mma_kernel<<<cgE, 256, TC_SMEM_BYTES>>>(pah, pal,
            pwh + base + 1 * WEE27, pwl + base + 1 * WEE27,
            bk + i * EE, nullptr, pk, nullptr, nullptr, 256, 256, 0);
        conv3d_mma_kernel<<<cgE, 256, TC_SMEM_BYTES>>>(pah, pal,
            pwh + base + 2 * WEE27, pwl + base + 2 * WEE27,
            bv + i * EE, nullptr, pv, nullptr, nullptr, 256, 256, 0);
        attn_kernel<<<4096, 128>>>(pq, pk, pv, pah, pal);
        conv3d_mma_kernel<<<cgE, 256, TC_SMEM_BYTES>>>(pah, pal,
            pwh + base + 3 * WEE27, pwl + base + 3 * WEE27,
            bo + i * EE, px, px, nullptr, nullptr, 256, 256, 0);
        ln_kernel<<<LN_BLOCKS, 256>>>(px, nullptr, pah, pal,
                                      ln2s + i * EE, ln2b + i * EE, ROWS);
        conv3d_mma_kernel<<<cgH, 256, TC_SMEM_BYTES>>>(pah, pal,
            pwh + base + 4 * WEE27, pwl + base + 4 * WEE27,
            b1 + i * HIDD, nullptr, nullptr, pbh, pbl, 256, 512, 1);
        conv3d_mma_kernel<<<cgE, 256, TC_SMEM_BYTES>>>(pbh, pbl,
            pwh + base + 4 * WEE27 + WEH27, pwl + base + 4 * WEE27 + WEH27,
            b2 + i * EE, px, px, nullptr, nullptr, 512, 256, 0);
    }

    ln_kernel<<<LN_BLOCKS, 256>>>(px, nullptr, pah, pal, lnfs, lnfb, ROWS);
    conv3d_mma_kernel<<<cgE, 256, TC_SMEM_BYTES>>>(pah, pal,
        pwh + offdec, pwl + offdec, decb, nullptr, pq, nullptr, nullptr, 256, 256, 1);
    ln_kernel<<<LN_BLOCKS, 256>>>(pq, pk, nullptr, nullptr, declns, declnb, ROWS);
    linear_kernel<<<dim3(ROWS / 64, NEE / 64), 256>>>(pk, linw, linb, plog);

    if (out_size >= SCORE_SIZE) {
        dim3 sg(16, 16, 16);
        score_kernel<<<sg, 256>>>(plog, out, out_size);
    }
    int write_code = (out_size >= SCORE_SIZE + 1 + NROWS) ? 1 : 0;
    loss_argmax_kernel<<<(NROWS * 32) / 256, 256>>>(plog, ncode, prl, out, write_code);

    int loss_off = -1;
    if (out_size == 1) loss_off = 0;
    else if (out_size > SCORE_SIZE) loss_off = SCORE_SIZE;
    if (loss_off >= 0)
        loss_reduce_kernel<<<1, 256>>>(prl, out, loss_off);
}